// round 15
// baseline (speedup 1.0000x reference)
#include <cuda_runtime.h>

namespace {
constexpr int B  = 2;
constexpr int C  = 32;
constexpr int H  = 192;
constexpr int W  = 256;
constexpr int JH = 12;
constexpr int JW = 16;
constexpr int J  = JH * JW;      // 192
constexpr int HW = H * W;
constexpr int N  = HW;           // 49152
constexpr int NITER = 10;
constexpr int PITCH = 260;       // %4==0; LDS.128 conflict-free
constexpr int NB = B * J;        // 384 blocks; co-resident
}

// Persistent scratch (device globals; no allocation allowed)
// Dense pull-exchange buffers: slot s in [1..NITER] holds iteration s-1 output.
__device__ float    g_mean[NB * C];
__device__ float    g_part[(size_t)(NITER + 1) * NB * 9 * C];
__device__ float    g_pden[(NITER + 1) * NB * 9];
__device__ unsigned g_ready[NB];   // monotonic: 1 = mean, it+2 = slot it+1

__device__ __forceinline__ size_t PART(int slot, int gb, int k) {
    return ((size_t)(slot * NB + gb) * 9 + k) * C;
}

// ---------------------------------------------------------------------------
// Packed f32x2 helpers (Blackwell packed FP32)
// ---------------------------------------------------------------------------
__device__ __forceinline__ void ffma2(unsigned long long& d,
                                      unsigned long long a, unsigned long long b) {
    asm("fma.rn.f32x2 %0, %1, %2, %0;" : "+l"(d) : "l"(a), "l"(b));
}
__device__ __forceinline__ float f2sum(unsigned long long v) {
    float lo, hi;
    asm("mov.b64 {%0, %1}, %2;" : "=f"(lo), "=f"(hi) : "l"(v));
    return lo + hi;
}
__device__ __forceinline__ void f2unpack(unsigned long long v, float& lo, float& hi) {
    asm("mov.b64 {%0, %1}, %2;" : "=f"(lo), "=f"(hi) : "l"(v));
}
__device__ __forceinline__ unsigned long long f2pack(float lo, float hi) {
    unsigned long long r;
    asm("mov.b64 %0, {%1, %2};" : "=l"(r) : "f"(lo), "f"(hi));
    return r;
}

__device__ __forceinline__ void st_release_u32(unsigned* p, unsigned v) {
    asm volatile("st.release.gpu.u32 [%0], %1;" :: "l"(p), "r"(v) : "memory");
}
__device__ __forceinline__ void poll_flag(const unsigned* p, unsigned expect) {
    unsigned v;
    do {
        asm volatile("ld.acquire.gpu.u32 %0, [%1];" : "=r"(v) : "l"(p) : "memory");
        if (v >= expect) return;
        __nanosleep(64);
    } while (true);
}

// ---------------------------------------------------------------------------
__global__ void k_reset() {
    int i = blockIdx.x * blockDim.x + threadIdx.x;
    if (i < NB) g_ready[i] = 0u;
}

// ---------------------------------------------------------------------------
// Fused SSN, pull-dense exchange. One CTA per (b, cell); 256 threads.
// ---------------------------------------------------------------------------
__global__ __launch_bounds__(256, 4) void k_fused(const float* __restrict__ feats,
                                                  float* __restrict__ gamma_out,
                                                  float* __restrict__ recon_out) {
    __shared__ __align__(16) float s_sh[9][C];          // neighbor spix / later fm
    __shared__ float sn_sh[9];
    __shared__ int   cell_sh[9];
    __shared__ int   contrib_sh[81];                    // [k][e] -> global block id
    __shared__ __align__(16) float s_own[9][C];         // own partials (this slot)
    __shared__ float s_ownden[9];
    __shared__ __align__(16) float pix_sh[C * PITCH];
    __shared__ __align__(16) float aff_sh[9][256];      // aliased as s_acc in reduce

    int blk = blockIdx.x;
    int b = blk / J, j = blk % J;
    int jy = j / JW, jx = j % JW;
    int bJ = b * J;
    int gb = bJ + j;
    int t = threadIdx.x;
    int wk = t >> 5, lane = t & 31;

    // neighbor + contributor tables (static for this block)
    if (t < 9) {
        int dy = t / 3 - 1, dx = t % 3 - 1;
        int ny = jy + dy, nx = jx + dx;
        cell_sh[t] = (ny >= 0 && ny < JH && nx >= 0 && nx < JW) ? ny * JW + nx : -1;
    }
    if (t < 81) {
        int k = t / 9, e = t % 9;
        int nyk = jy + k / 3 - 1, nxk = jx + k % 3 - 1;
        int v = -1;
        if (nyk >= 0 && nyk < JH && nxk >= 0 && nxk < JW) {
            int ny2 = nyk + e / 3 - 1, nx2 = nxk + e % 3 - 1;
            if (ny2 >= 0 && ny2 < JH && nx2 >= 0 && nx2 < JW)
                v = bJ + ny2 * JW + nx2;
        }
        contrib_sh[t] = v;
    }

    // load pixel features ONCE into smem; compute |f|^2 (fn persists, 1 reg)
    int py = t >> 4, px = t & 15;
    int y = jy * 16 + py, x = jx * 16 + px;
    int n = y * W + x;
    const float* fp = feats + (size_t)b * C * HW + n;
    float fn;
    {
        unsigned long long fn2 = 0ull;
        #pragma unroll
        for (int i = 0; i < 16; i++) {
            float lo = fp[(2 * i) * HW];
            float hi = fp[(2 * i + 1) * HW];
            pix_sh[(2 * i) * PITCH + t]     = lo;
            pix_sh[(2 * i + 1) * PITCH + t] = hi;
            unsigned long long v = f2pack(lo, hi);
            ffma2(fn2, v, v);
        }
        fn = f2sum(fn2);
    }
    __syncthreads();   // pix_sh + tables ready

    // mean over own 16x16 cell (warp slices -> tree); publish ASAP
    {
        const float* pr = &pix_sh[lane * PITCH + wk * 32];
        float ms = 0.0f;
        #pragma unroll
        for (int i = 0; i < 32; i += 4) {
            float4 v = *(const float4*)&pr[i];
            ms += (v.x + v.y) + (v.z + v.w);
        }
        ((float*)aff_sh)[wk * 32 + lane] = ms;
        __syncthreads();
        if (wk == 0) {
            float s = 0.0f;
            #pragma unroll
            for (int w2 = 0; w2 < 8; w2++) s += ((float*)aff_sh)[w2 * 32 + lane];
            g_mean[gb * C + lane] = s * (1.0f / 256.0f);
            __syncwarp();
            if (lane == 0) st_release_u32(&g_ready[gb], 1u);   // mean published
        }
    }

    // stream the ~183 all-zero gamma planes now (overlaps the iteration loop)
    {
        int q = t & 63, jr = t >> 6;
        int r = q >> 2, colq = q & 3;
        size_t rowoff = (size_t)(jy * 16 + r) * W + jx * 16 + colq * 4;
        const float4 z = make_float4(0.f, 0.f, 0.f, 0.f);
        #pragma unroll 4
        for (int i = 0; i < 48; i++) {
            int jv  = jr + (i << 2);
            int jjy = jv >> 4, jjx = jv & 15;
            int ddy = jjy - jy, ddx = jjx - jx;
            if (ddy < -1 || ddy > 1 || ddx < -1 || ddx > 1)
                __stcs((float4*)&gamma_out[((size_t)(bJ + jv)) * N + rowoff], z);
        }
    }

    float a[9];               // own-pixel affinities (persist to finale)

    for (int it = 0; it < NITER; it++) {
        // ---- phase 0: pull neighbor spix (slot `it`) ----
        for (int k = wk; k < 9; k += 8) {
            int nc = cell_sh[k];
            float sv = 0.0f;
            if (nc >= 0) {
                if (it == 0) {
                    poll_flag(&g_ready[bJ + nc], 1u);
                    sv = __ldcg(&g_mean[(bJ + nc) * C + lane]);
                } else {
                    int self_e = 8 - k;
                    int jcl = (lane < 9) ? contrib_sh[k * 9 + lane] : -1;
                    if (jcl >= 0 && lane != self_e)
                        poll_flag(&g_ready[jcl], (unsigned)(it + 1));
                    __syncwarp();
                    float acc = s_own[k][lane];        // own partial (e = 8-k)
                    #pragma unroll
                    for (int e = 0; e < 9; e++) {
                        if (e == self_e) continue;
                        int jce = contrib_sh[k * 9 + e];
                        if (jce >= 0)
                            acc += __ldcg(&g_part[PART(it, jce, 8 - e) + lane]);
                    }
                    float dl = 0.0f;
                    if (lane < 9) {
                        if (lane == self_e) dl = s_ownden[k];
                        else if (jcl >= 0)
                            dl = __ldcg(&g_pden[(it * NB + jcl) * 9 + (8 - lane)]);
                    }
                    #pragma unroll
                    for (int o = 16; o; o >>= 1)
                        dl += __shfl_xor_sync(0xffffffffu, dl, o);
                    sv = acc / (dl + 1e-16f);
                }
            }
            s_sh[k][lane] = sv;
            float sq = sv * sv;
            #pragma unroll
            for (int o = 16; o; o >>= 1) sq += __shfl_xor_sync(0xffffffffu, sq, o);
            if (lane == 0) sn_sh[k] = sq;
        }
        __syncthreads();

        // ---- phase 1: distances (f32x2 FMA; f repacked from smem) + softmax ----
        unsigned long long d2[9];
        #pragma unroll
        for (int k = 0; k < 9; k++) d2[k] = 0ull;
        #pragma unroll
        for (int c4 = 0; c4 < 8; c4++) {
            float fa = pix_sh[(4 * c4 + 0) * PITCH + t];
            float fb = pix_sh[(4 * c4 + 1) * PITCH + t];
            float fc = pix_sh[(4 * c4 + 2) * PITCH + t];
            float fd = pix_sh[(4 * c4 + 3) * PITCH + t];
            unsigned long long fx = f2pack(fa, fb);
            unsigned long long fy = f2pack(fc, fd);
            #pragma unroll
            for (int k = 0; k < 9; k++) {
                ulonglong2 sv = ((const ulonglong2*)s_sh[k])[c4];
                ffma2(d2[k], fx, sv.x);
                ffma2(d2[k], fy, sv.y);
            }
        }
        float dist[9];
        #pragma unroll
        for (int k = 0; k < 9; k++)
            dist[k] = fn - 2.0f * f2sum(d2[k]) + sn_sh[k];

        float m = 3.0e38f;
        #pragma unroll
        for (int k = 0; k < 9; k++)
            if (cell_sh[k] >= 0) m = fminf(m, dist[k]);
        float sum = 0.0f;
        #pragma unroll
        for (int k = 0; k < 9; k++) {
            a[k] = (cell_sh[k] >= 0) ? __expf(m - dist[k]) : 0.0f;
            sum += a[k];
        }
        float inv = 1.0f / sum;
        #pragma unroll
        for (int k = 0; k < 9; k++) {
            a[k] *= inv;
            aff_sh[k][t] = a[k];
        }
        __syncthreads();

        // ---- phase 2: warp-slice accumulation (lane = channel), f32x2 ----
        unsigned long long acc2[9];
        #pragma unroll
        for (int k = 0; k < 9; k++) acc2[k] = 0ull;
        {
            int p0 = wk * 32;
            const float* pr = &pix_sh[lane * PITCH + p0];
            #pragma unroll
            for (int i = 0; i < 32; i += 4) {
                ulonglong2 pv = *(const ulonglong2*)&pr[i];
                #pragma unroll
                for (int k = 0; k < 9; k++) {
                    ulonglong2 av = *(const ulonglong2*)&aff_sh[k][p0 + i];  // bcast
                    ffma2(acc2[k], av.x, pv.x);
                    ffma2(acc2[k], av.y, pv.y);
                }
            }
        }
        // denominators (read aff_sh before it is aliased); lane 0 holds result
        float dreg[2] = {0.0f, 0.0f};
        {
            int nd = 0;
            for (int k = wk; k < 9; k += 8) {
                float d = 0.0f;
                #pragma unroll
                for (int i2 = 0; i2 < 8; i2++) d += aff_sh[k][lane + (i2 << 5)];
                #pragma unroll
                for (int o = 16; o; o >>= 1) d += __shfl_xor_sync(0xffffffffu, d, o);
                dreg[nd++] = d;
            }
        }
        __syncthreads();                       // aff_sh + pix_sh reads done
        if (it == NITER - 1) {                 // stash affinities for the finale
            #pragma unroll
            for (int k = 0; k < 9; k++) pix_sh[k * 256 + t] = a[k];
        }
        float* s_acc = (float*)aff_sh;         // [8][9][32]
        #pragma unroll
        for (int k = 0; k < 9; k++)
            s_acc[(wk * 9 + k) * 32 + lane] = f2sum(acc2[k]);
        __syncthreads();

        // ---- tree reduce + DENSE stores (no atomics) + single release ----
        {
            int slot = it + 1;
            int nd = 0;
            for (int k = wk; k < 9; k += 8) {
                int nc = cell_sh[k];
                float dv = dreg[nd++];
                if (nc >= 0) {
                    float v = 0.0f;
                    #pragma unroll
                    for (int w2 = 0; w2 < 8; w2++)
                        v += s_acc[(w2 * 9 + k) * 32 + lane];
                    g_part[PART(slot, gb, k) + lane] = v;
                    s_own[k][lane] = v;
                    if (lane == 0) {
                        g_pden[(slot * NB + gb) * 9 + k] = dv;
                        s_ownden[k] = dv;
                    }
                }
            }
        }
        __syncthreads();                       // all warps' stores done
        if (t == 0) st_release_u32(&g_ready[gb], (unsigned)(it + 2));
    }

    // =======================================================================
    // Finale: the 9 affinity gamma planes (zeros already streamed), then
    // fm (pulled from slot NITER) + recon.
    // =======================================================================
    const float* aff2 = pix_sh;
    {
        int q = t & 63, jr = t >> 6;
        int r = q >> 2, colq = q & 3;
        size_t rowoff = (size_t)(jy * 16 + r) * W + jx * 16 + colq * 4;
        for (int k = jr; k < 9; k += 4) {
            int jv = cell_sh[k];
            if (jv >= 0) {
                float4 v = *(const float4*)&aff2[k * 256 + r * 16 + colq * 4];
                __stcs((float4*)&gamma_out[((size_t)(bJ + jv)) * N + rowoff], v);
            }
        }
    }

    // fm = (sum of slot-10 partials)/(sum dens + 1e-6)
    for (int k = wk; k < 9; k += 8) {
        int nc = cell_sh[k];
        float fv = 0.0f;
        if (nc >= 0) {
            int self_e = 8 - k;
            int jcl = (lane < 9) ? contrib_sh[k * 9 + lane] : -1;
            if (jcl >= 0 && lane != self_e)
                poll_flag(&g_ready[jcl], (unsigned)(NITER + 1));
            __syncwarp();
            float acc = s_own[k][lane];
            #pragma unroll
            for (int e = 0; e < 9; e++) {
                if (e == self_e) continue;
                int jce = contrib_sh[k * 9 + e];
                if (jce >= 0)
                    acc += __ldcg(&g_part[PART(NITER, jce, 8 - e) + lane]);
            }
            float dl = 0.0f;
            if (lane < 9) {
                if (lane == self_e) dl = s_ownden[k];
                else if (jcl >= 0)
                    dl = __ldcg(&g_pden[(NITER * NB + jcl) * 9 + (8 - lane)]);
            }
            #pragma unroll
            for (int o = 16; o; o >>= 1) dl += __shfl_xor_sync(0xffffffffu, dl, o);
            fv = acc / (dl + 1e-6f);
        }
        s_sh[k][lane] = fv;
    }
    __syncthreads();

    // recon[b,c,n] = sum_k a[k] * fm[cell_k][c]   (f32x2)
    unsigned long long rec2[16];
    #pragma unroll
    for (int i = 0; i < 16; i++) rec2[i] = 0ull;
    #pragma unroll
    for (int k = 0; k < 9; k++) {
        unsigned long long ak2 = f2pack(a[k], a[k]);
        const ulonglong2* s2 = (const ulonglong2*)s_sh[k];
        #pragma unroll
        for (int c4 = 0; c4 < 8; c4++) {
            ulonglong2 sv = s2[c4];
            ffma2(rec2[2 * c4],     ak2, sv.x);
            ffma2(rec2[2 * c4 + 1], ak2, sv.y);
        }
    }
    #pragma unroll
    for (int i = 0; i < 16; i++) {
        float lo, hi;
        f2unpack(rec2[i], lo, hi);
        __stcs(&recon_out[((size_t)(b * C + 2 * i) * H + y) * W + x], lo);
        __stcs(&recon_out[((size_t)(b * C + 2 * i + 1) * H + y) * W + x], hi);
    }
}

// ---------------------------------------------------------------------------
extern "C" void kernel_launch(void* const* d_in, const int* in_sizes, int n_in,
                              void* d_out, int out_size) {
    (void)in_sizes; (void)n_in; (void)out_size;
    const float* feats = (const float*)d_in[0];
    float* gamma = (float*)d_out;
    float* recon = gamma + (size_t)B * J * N;

    k_reset<<<2, 256>>>();
    k_fused<<<NB, 256>>>(feats, gamma, recon);
}

// round 16
// speedup vs baseline: 2.0750x; 2.0750x over previous
#include <cuda_runtime.h>

namespace {
constexpr int B  = 2;
constexpr int C  = 32;
constexpr int H  = 192;
constexpr int W  = 256;
constexpr int JH = 12;
constexpr int JW = 16;
constexpr int J  = JH * JW;      // 192
constexpr int HW = H * W;
constexpr int N  = HW;           // 49152
constexpr int NITER = 10;
constexpr int SLOTS = NITER + 1; // slot 0 = init, slots 1..10 = iteration results
constexpr int PITCH = 260;       // %4==0; LDS.128 conflict-free
constexpr int NB = B * J;        // 384 blocks; co-resident
}

// Persistent scratch (device globals; no allocation allowed)
__device__ float    g_num[SLOTS][B * J * C];
__device__ float    g_den[SLOTS][B * J];
__device__ unsigned g_flag[SLOTS][B * J];

// ---------------------------------------------------------------------------
// Packed f32x2 helpers (Blackwell packed FP32)
// ---------------------------------------------------------------------------
__device__ __forceinline__ void ffma2(unsigned long long& d,
                                      unsigned long long a, unsigned long long b) {
    asm("fma.rn.f32x2 %0, %1, %2, %0;" : "+l"(d) : "l"(a), "l"(b));
}
__device__ __forceinline__ float f2sum(unsigned long long v) {
    float lo, hi;
    asm("mov.b64 {%0, %1}, %2;" : "=f"(lo), "=f"(hi) : "l"(v));
    return lo + hi;
}
__device__ __forceinline__ void f2unpack(unsigned long long v, float& lo, float& hi) {
    asm("mov.b64 {%0, %1}, %2;" : "=f"(lo), "=f"(hi) : "l"(v));
}
__device__ __forceinline__ unsigned long long f2pack(float lo, float hi) {
    unsigned long long r;
    asm("mov.b64 %0, {%1, %2};" : "=l"(r) : "f"(lo), "f"(hi));
    return r;
}
// Release-reduction on a flag: orders THIS thread's prior ops; combined with
// the preceding __syncwarp() (memory-ordering among participants), it covers
// the whole warp's atomics. Pattern correctness-proven in R10/R12 runs.
__device__ __forceinline__ void red_add_release_u32(unsigned* p, unsigned v) {
    asm volatile("red.release.gpu.global.add.u32 [%0], %1;" :: "l"(p), "r"(v) : "memory");
}

// ---------------------------------------------------------------------------
__global__ void k_reset() {
    int i = blockIdx.x * blockDim.x + threadIdx.x;
    if (i < SLOTS * B * J) (&g_flag[0][0])[i] = 0u;
}

__device__ __forceinline__ void poll_flag(const unsigned* p, unsigned expect) {
    unsigned v;
    do {
        asm volatile("ld.acquire.gpu.u32 %0, [%1];" : "=r"(v) : "l"(p) : "memory");
        if (v >= expect) return;
        __nanosleep(64);
    } while (true);
}

// ---------------------------------------------------------------------------
// Fused SSN (champion engine): init + 10 iterations + finale, one kernel.
// One CTA per (b, cell); 256 threads. Push exchange, destination summation,
// per-warp release publish (no block-wide threadfence in the loop).
// ---------------------------------------------------------------------------
__global__ __launch_bounds__(256, 4) void k_fused(const float* __restrict__ feats,
                                                  float* __restrict__ gamma_out,
                                                  float* __restrict__ recon_out) {
    __shared__ __align__(16) float s_sh[9][C];          // neighbor spix / later fm
    __shared__ float sn_sh[9];
    __shared__ int   cell_sh[9];
    __shared__ int   expect_sh[9];
    __shared__ __align__(16) float pix_sh[C * PITCH];
    __shared__ __align__(16) float aff_sh[9][256];      // aliased as s_acc in reduce

    int blk = blockIdx.x;
    int b = blk / J, j = blk % J;
    int jy = j / JW, jx = j % JW;
    int bJ = b * J;
    int t = threadIdx.x;
    int wk = t >> 5, lane = t & 31;

    // neighbor table + expected contributor counts (static)
    if (t < 9) {
        int dy = t / 3 - 1, dx = t % 3 - 1;
        int ny = jy + dy, nx = jx + dx;
        int nc = (ny >= 0 && ny < JH && nx >= 0 && nx < JW) ? ny * JW + nx : -1;
        cell_sh[t] = nc;
        int ex = 0;
        if (nc >= 0) {
            int cy = 3 - (ny == 0) - (ny == JH - 1);
            int cx = 3 - (nx == 0) - (nx == JW - 1);
            ex = cy * cx;
        }
        expect_sh[t] = ex;
    }

    // load pixel features ONCE into smem; compute |f|^2 (fn persists, 1 reg)
    int py = t >> 4, px = t & 15;
    int y = jy * 16 + py, x = jx * 16 + px;
    int n = y * W + x;
    const float* fp = feats + (size_t)b * C * HW + n;
    float fn;
    {
        unsigned long long fn2 = 0ull;
        #pragma unroll
        for (int i = 0; i < 16; i++) {
            float lo = fp[(2 * i) * HW];
            float hi = fp[(2 * i + 1) * HW];
            pix_sh[(2 * i) * PITCH + t]     = lo;
            pix_sh[(2 * i + 1) * PITCH + t] = hi;
            unsigned long long v = f2pack(lo, hi);
            ffma2(fn2, v, v);
        }
        fn = f2sum(fn2);
    }

    // zero own cell's slots 1..10; write slot-0 den
    if (t < C) {
        #pragma unroll
        for (int s = 1; s < SLOTS; s++) g_num[s][(bJ + j) * C + t] = 0.0f;
    }
    if (t == C) {
        #pragma unroll
        for (int s = 1; s < SLOTS; s++) g_den[s][bJ + j] = 0.0f;
        g_den[0][bJ + j] = 256.0f;   // so num/(den+eps) == cell mean exactly
    }
    __syncthreads();   // pix_sh + tables ready

    // slot-0 num = per-channel sum over own 16x16 cell (warp slices -> tree)
    {
        const float* pr = &pix_sh[lane * PITCH + wk * 32];
        float ms = 0.0f;
        #pragma unroll
        for (int i = 0; i < 32; i += 4) {
            float4 v = *(const float4*)&pr[i];
            ms += (v.x + v.y) + (v.z + v.w);
        }
        ((float*)aff_sh)[wk * 32 + lane] = ms;
        __syncthreads();
        if (wk == 0) {
            float s = 0.0f;
            #pragma unroll
            for (int w2 = 0; w2 < 8; w2++) s += ((float*)aff_sh)[w2 * 32 + lane];
            g_num[0][(bJ + j) * C + lane] = s;
        }
    }
    __threadfence();   // one-time init publish (kept conservative)
    __syncthreads();
    if (t == 0) atomicAdd(&g_flag[0][bJ + j], 1u);   // publish slot 0 (expect 1)

    float a[9];               // own-pixel affinities (persist to finale)

    for (int it = 0; it < NITER; it++) {
        // ---- phase 0: wait for + load neighbor spix from slot `it` ----
        for (int k = wk; k < 9; k += 8) {
            int nc = cell_sh[k];
            float sv = 0.0f;
            if (nc >= 0) {
                int idx = bJ + nc;
                unsigned ex = (it == 0) ? 1u : (unsigned)expect_sh[k];
                poll_flag(&g_flag[it][idx], ex);             // all lanes, acquire
                sv = __ldcg(&g_num[it][idx * C + lane]) /
                     (__ldcg(&g_den[it][idx]) + 1e-16f);
            }
            s_sh[k][lane] = sv;
            float sq = sv * sv;
            #pragma unroll
            for (int o = 16; o; o >>= 1) sq += __shfl_xor_sync(0xffffffffu, sq, o);
            if (lane == 0) sn_sh[k] = sq;
        }
        __syncthreads();

        // ---- phase 1: distances (f32x2 FMA; f repacked from smem) + softmax ----
        unsigned long long d2[9];
        #pragma unroll
        for (int k = 0; k < 9; k++) d2[k] = 0ull;
        #pragma unroll
        for (int c4 = 0; c4 < 8; c4++) {
            float fa = pix_sh[(4 * c4 + 0) * PITCH + t];
            float fb = pix_sh[(4 * c4 + 1) * PITCH + t];
            float fc = pix_sh[(4 * c4 + 2) * PITCH + t];
            float fd = pix_sh[(4 * c4 + 3) * PITCH + t];
            unsigned long long fx = f2pack(fa, fb);
            unsigned long long fy = f2pack(fc, fd);
            #pragma unroll
            for (int k = 0; k < 9; k++) {
                ulonglong2 sv = ((const ulonglong2*)s_sh[k])[c4];
                ffma2(d2[k], fx, sv.x);
                ffma2(d2[k], fy, sv.y);
            }
        }
        float dist[9];
        #pragma unroll
        for (int k = 0; k < 9; k++)
            dist[k] = fn - 2.0f * f2sum(d2[k]) + sn_sh[k];

        float m = 3.0e38f;
        #pragma unroll
        for (int k = 0; k < 9; k++)
            if (cell_sh[k] >= 0) m = fminf(m, dist[k]);
        float sum = 0.0f;
        #pragma unroll
        for (int k = 0; k < 9; k++) {
            a[k] = (cell_sh[k] >= 0) ? __expf(m - dist[k]) : 0.0f;
            sum += a[k];
        }
        float inv = 1.0f / sum;
        #pragma unroll
        for (int k = 0; k < 9; k++) {
            a[k] *= inv;
            aff_sh[k][t] = a[k];
        }
        __syncthreads();

        // ---- phase 2: warp-slice accumulation (lane = channel), f32x2 ----
        unsigned long long acc2[9];
        #pragma unroll
        for (int k = 0; k < 9; k++) acc2[k] = 0ull;
        {
            int p0 = wk * 32;
            const float* pr = &pix_sh[lane * PITCH + p0];
            #pragma unroll
            for (int i = 0; i < 32; i += 4) {
                ulonglong2 pv = *(const ulonglong2*)&pr[i];
                #pragma unroll
                for (int k = 0; k < 9; k++) {
                    ulonglong2 av = *(const ulonglong2*)&aff_sh[k][p0 + i];  // bcast
                    ffma2(acc2[k], av.x, pv.x);
                    ffma2(acc2[k], av.y, pv.y);
                }
            }
        }
        // denominators (read aff_sh before it is aliased); lane 0 holds result
        float dreg[2] = {0.0f, 0.0f};
        {
            int nd = 0;
            for (int k = wk; k < 9; k += 8) {
                float d = 0.0f;
                #pragma unroll
                for (int i2 = 0; i2 < 8; i2++) d += aff_sh[k][lane + (i2 << 5)];
                #pragma unroll
                for (int o = 16; o; o >>= 1) d += __shfl_xor_sync(0xffffffffu, d, o);
                dreg[nd++] = d;
            }
        }
        __syncthreads();                       // aff_sh + pix_sh reads done
        if (it == NITER - 1) {                 // stash affinities for the finale
            #pragma unroll
            for (int k = 0; k < 9; k++) pix_sh[k * 256 + t] = a[k];
        }
        float* s_acc = (float*)aff_sh;         // [8][9][32]
        #pragma unroll
        for (int k = 0; k < 9; k++)
            s_acc[(wk * 9 + k) * 32 + lane] = f2sum(acc2[k]);
        __syncthreads();

        // ---- tree reduce + atomics + per-warp RELEASE publish (no fence) ----
        {
            int nd = 0;
            for (int k = wk; k < 9; k += 8) {
                int nc = cell_sh[k];
                float dv = dreg[nd++];
                if (nc >= 0) {
                    float v = 0.0f;
                    #pragma unroll
                    for (int w2 = 0; w2 < 8; w2++)
                        v += s_acc[(w2 * 9 + k) * 32 + lane];
                    atomicAdd(&g_num[it + 1][(bJ + nc) * C + lane], v);
                    if (lane == 0) atomicAdd(&g_den[it + 1][bJ + nc], dv);
                }
            }
        }
        __syncwarp();   // memory-ordering among warp lanes: all num/den posted
        for (int k = wk; k < 9; k += 8) {
            int nc = cell_sh[k];
            if (nc >= 0 && lane == 0)
                red_add_release_u32(&g_flag[it + 1][bJ + nc], 1u);
        }
    }

    // =======================================================================
    // Finale: gamma first (depends only on stashed aff), then fm + recon.
    // =======================================================================
    const float* aff2 = pix_sh;
    {
        int q = t & 63, jr = t >> 6;
        int r = q >> 2, colq = q & 3;
        size_t rowoff = (size_t)(jy * 16 + r) * W + jx * 16 + colq * 4;
        #pragma unroll 4
        for (int i = 0; i < 48; i++) {
            int jv  = jr + (i << 2);
            int jjy = jv >> 4, jjx = jv & 15;
            int ddy = jjy - jy, ddx = jjx - jx;
            float4 v = make_float4(0.f, 0.f, 0.f, 0.f);
            if (ddy >= -1 && ddy <= 1 && ddx >= -1 && ddx <= 1) {
                int k = (ddy + 1) * 3 + (ddx + 1);
                v = *(const float4*)&aff2[k * 256 + r * 16 + colq * 4];
            }
            __stcs((float4*)&gamma_out[((size_t)(bJ + jv)) * N + rowoff], v);
        }
    }

    // fm = num[10]/(den[10]+1e-6), gated on slot-10 flags
    for (int k = wk; k < 9; k += 8) {
        int nc = cell_sh[k];
        float fv = 0.0f;
        if (nc >= 0) {
            int idx = bJ + nc;
            poll_flag(&g_flag[NITER][idx], (unsigned)expect_sh[k]);
            fv = __ldcg(&g_num[NITER][idx * C + lane]) /
                 (__ldcg(&g_den[NITER][idx]) + 1e-6f);
        }
        s_sh[k][lane] = fv;
    }
    __syncthreads();

    // recon[b,c,n] = sum_k a[k] * fm[cell_k][c]   (f32x2)
    unsigned long long rec2[16];
    #pragma unroll
    for (int i = 0; i < 16; i++) rec2[i] = 0ull;
    #pragma unroll
    for (int k = 0; k < 9; k++) {
        unsigned long long ak2 = f2pack(a[k], a[k]);
        const ulonglong2* s2 = (const ulonglong2*)s_sh[k];
        #pragma unroll
        for (int c4 = 0; c4 < 8; c4++) {
            ulonglong2 sv = s2[c4];
            ffma2(rec2[2 * c4],     ak2, sv.x);
            ffma2(rec2[2 * c4 + 1], ak2, sv.y);
        }
    }
    #pragma unroll
    for (int i = 0; i < 16; i++) {
        float lo, hi;
        f2unpack(rec2[i], lo, hi);
        __stcs(&recon_out[((size_t)(b * C + 2 * i) * H + y) * W + x], lo);
        __stcs(&recon_out[((size_t)(b * C + 2 * i + 1) * H + y) * W + x], hi);
    }
}

// ---------------------------------------------------------------------------
extern "C" void kernel_launch(void* const* d_in, const int* in_sizes, int n_in,
                              void* d_out, int out_size) {
    (void)in_sizes; (void)n_in; (void)out_size;
    const float* feats = (const float*)d_in[0];
    float* gamma = (float*)d_out;
    float* recon = gamma + (size_t)B * J * N;

    k_reset<<<(SLOTS * B * J + 255) / 256, 256>>>();
    k_fused<<<NB, 256>>>(feats, gamma, recon);
}

// round 17
// speedup vs baseline: 2.1445x; 1.0335x over previous
#include <cuda_runtime.h>

namespace {
constexpr int B  = 2;
constexpr int C  = 32;
constexpr int H  = 192;
constexpr int W  = 256;
constexpr int JH = 12;
constexpr int JW = 16;
constexpr int J  = JH * JW;      // 192
constexpr int HW = H * W;
constexpr int N  = HW;           // 49152
constexpr int NITER = 10;
constexpr int SLOTS = NITER + 1; // slot 0 = init, slots 1..10 = iteration results
constexpr int PITCH = 260;       // %4==0; LDS.128 conflict-free
constexpr int NB = B * J;        // 384 blocks; co-resident
}

// Persistent scratch (device globals; no allocation allowed)
__device__ float    g_num[SLOTS][B * J * C];
__device__ float    g_den[SLOTS][B * J];
__device__ unsigned g_flag[SLOTS][B * J];

// ---------------------------------------------------------------------------
// Packed f32x2 helpers (Blackwell packed FP32)
// ---------------------------------------------------------------------------
__device__ __forceinline__ void ffma2(unsigned long long& d,
                                      unsigned long long a, unsigned long long b) {
    asm("fma.rn.f32x2 %0, %1, %2, %0;" : "+l"(d) : "l"(a), "l"(b));
}
__device__ __forceinline__ float f2sum(unsigned long long v) {
    float lo, hi;
    asm("mov.b64 {%0, %1}, %2;" : "=f"(lo), "=f"(hi) : "l"(v));
    return lo + hi;
}
__device__ __forceinline__ void f2unpack(unsigned long long v, float& lo, float& hi) {
    asm("mov.b64 {%0, %1}, %2;" : "=f"(lo), "=f"(hi) : "l"(v));
}
__device__ __forceinline__ unsigned long long f2pack(float lo, float hi) {
    unsigned long long r;
    asm("mov.b64 %0, {%1, %2};" : "=l"(r) : "f"(lo), "f"(hi));
    return r;
}

// ---------------------------------------------------------------------------
// MUFU-free exp for x <= 0: exp(x) = 2^(x*log2e), runs on FMA/ALU pipes.
// Magic-number rounding + degree-5 poly for 2^f on [-0.5, 0.5] (rel ~2e-6),
// exponent spliced by integer add on the float bits (safe: p in [0.70,1.42],
// ei in [-126, 0] -> biased exponent stays in [0, 127]).
// ---------------------------------------------------------------------------
__device__ __forceinline__ float fexp_neg(float x) {
    float t = x * 1.4426950408889634f;
    t = fmaxf(t, -126.0f);
    float z  = t + 12582912.0f;            // round-to-nearest-int in mantissa
    float fi = z - 12582912.0f;            // exact integer part (as float)
    float f  = t - fi;                     // [-0.5, 0.5]
    float p  = 1.33335581e-3f;
    p = fmaf(p, f, 9.61812911e-3f);
    p = fmaf(p, f, 5.55041087e-2f);
    p = fmaf(p, f, 2.40226507e-1f);
    p = fmaf(p, f, 6.93147181e-1f);
    p = fmaf(p, f, 1.0f);
    int ei = (int)fi;
    return __int_as_float(__float_as_int(p) + (ei << 23));
}

// ---------------------------------------------------------------------------
__global__ void k_reset() {
    int i = blockIdx.x * blockDim.x + threadIdx.x;
    if (i < SLOTS * B * J) (&g_flag[0][0])[i] = 0u;
}

__device__ __forceinline__ void poll_flag(const unsigned* p, unsigned expect) {
    unsigned v;
    do {
        asm volatile("ld.acquire.gpu.u32 %0, [%1];" : "=r"(v) : "l"(p) : "memory");
        if (v >= expect) return;
        __nanosleep(64);
    } while (true);
}

// ---------------------------------------------------------------------------
// Fused SSN champion engine + MUFU-free softmax exp.
// One CTA per (b, cell); 256 threads. Cross-cell sync via per-cell flags.
// ---------------------------------------------------------------------------
__global__ __launch_bounds__(256, 4) void k_fused(const float* __restrict__ feats,
                                                  float* __restrict__ gamma_out,
                                                  float* __restrict__ recon_out) {
    __shared__ __align__(16) float s_sh[9][C];          // neighbor spix / later fm
    __shared__ float sn_sh[9];
    __shared__ int   cell_sh[9];
    __shared__ int   expect_sh[9];
    __shared__ __align__(16) float pix_sh[C * PITCH];
    __shared__ __align__(16) float aff_sh[9][256];      // aliased as s_acc in reduce

    int blk = blockIdx.x;
    int b = blk / J, j = blk % J;
    int jy = j / JW, jx = j % JW;
    int bJ = b * J;
    int t = threadIdx.x;
    int wk = t >> 5, lane = t & 31;

    // neighbor table + expected contributor counts (static)
    if (t < 9) {
        int dy = t / 3 - 1, dx = t % 3 - 1;
        int ny = jy + dy, nx = jx + dx;
        int nc = (ny >= 0 && ny < JH && nx >= 0 && nx < JW) ? ny * JW + nx : -1;
        cell_sh[t] = nc;
        int ex = 0;
        if (nc >= 0) {
            int cy = 3 - (ny == 0) - (ny == JH - 1);
            int cx = 3 - (nx == 0) - (nx == JW - 1);
            ex = cy * cx;
        }
        expect_sh[t] = ex;
    }

    // load pixel features ONCE into smem; compute |f|^2 (fn persists, 1 reg)
    int py = t >> 4, px = t & 15;
    int y = jy * 16 + py, x = jx * 16 + px;
    int n = y * W + x;
    const float* fp = feats + (size_t)b * C * HW + n;
    float fn;
    {
        unsigned long long fn2 = 0ull;
        #pragma unroll
        for (int i = 0; i < 16; i++) {
            float lo = fp[(2 * i) * HW];
            float hi = fp[(2 * i + 1) * HW];
            pix_sh[(2 * i) * PITCH + t]     = lo;
            pix_sh[(2 * i + 1) * PITCH + t] = hi;
            unsigned long long v = f2pack(lo, hi);
            ffma2(fn2, v, v);
        }
        fn = f2sum(fn2);
    }

    // zero own cell's slots 1..10; write slot-0 den
    if (t < C) {
        #pragma unroll
        for (int s = 1; s < SLOTS; s++) g_num[s][(bJ + j) * C + t] = 0.0f;
    }
    if (t == C) {
        #pragma unroll
        for (int s = 1; s < SLOTS; s++) g_den[s][bJ + j] = 0.0f;
        g_den[0][bJ + j] = 256.0f;   // so num/(den+eps) == cell mean exactly
    }
    __syncthreads();   // pix_sh + tables ready

    // slot-0 num = per-channel sum over own 16x16 cell (warp slices -> tree)
    {
        const float* pr = &pix_sh[lane * PITCH + wk * 32];
        float ms = 0.0f;
        #pragma unroll
        for (int i = 0; i < 32; i += 4) {
            float4 v = *(const float4*)&pr[i];
            ms += (v.x + v.y) + (v.z + v.w);
        }
        ((float*)aff_sh)[wk * 32 + lane] = ms;
        __syncthreads();
        if (wk == 0) {
            float s = 0.0f;
            #pragma unroll
            for (int w2 = 0; w2 < 8; w2++) s += ((float*)aff_sh)[w2 * 32 + lane];
            g_num[0][(bJ + j) * C + lane] = s;
        }
    }
    __threadfence();
    __syncthreads();
    if (t == 0) atomicAdd(&g_flag[0][bJ + j], 1u);   // publish slot 0 (expect 1)

    float a[9];               // own-pixel affinities (persist to finale)

    for (int it = 0; it < NITER; it++) {
        // ---- phase 0: wait for + load neighbor spix from slot `it` ----
        for (int k = wk; k < 9; k += 8) {
            int nc = cell_sh[k];
            float sv = 0.0f;
            if (nc >= 0) {
                int idx = bJ + nc;
                unsigned ex = (it == 0) ? 1u : (unsigned)expect_sh[k];
                poll_flag(&g_flag[it][idx], ex);             // all lanes, acquire
                sv = __ldcg(&g_num[it][idx * C + lane]) /
                     (__ldcg(&g_den[it][idx]) + 1e-16f);
            }
            s_sh[k][lane] = sv;
            float sq = sv * sv;
            #pragma unroll
            for (int o = 16; o; o >>= 1) sq += __shfl_xor_sync(0xffffffffu, sq, o);
            if (lane == 0) sn_sh[k] = sq;
        }
        __syncthreads();

        // ---- phase 1: distances (f32x2 FMA; f repacked from smem) + softmax ----
        unsigned long long d2[9];
        #pragma unroll
        for (int k = 0; k < 9; k++) d2[k] = 0ull;
        #pragma unroll
        for (int c4 = 0; c4 < 8; c4++) {
            float fa = pix_sh[(4 * c4 + 0) * PITCH + t];
            float fb = pix_sh[(4 * c4 + 1) * PITCH + t];
            float fc = pix_sh[(4 * c4 + 2) * PITCH + t];
            float fd = pix_sh[(4 * c4 + 3) * PITCH + t];
            unsigned long long fx = f2pack(fa, fb);
            unsigned long long fy = f2pack(fc, fd);
            #pragma unroll
            for (int k = 0; k < 9; k++) {
                ulonglong2 sv = ((const ulonglong2*)s_sh[k])[c4];
                ffma2(d2[k], fx, sv.x);
                ffma2(d2[k], fy, sv.y);
            }
        }
        float dist[9];
        #pragma unroll
        for (int k = 0; k < 9; k++)
            dist[k] = fn - 2.0f * f2sum(d2[k]) + sn_sh[k];

        float m = 3.0e38f;
        #pragma unroll
        for (int k = 0; k < 9; k++)
            if (cell_sh[k] >= 0) m = fminf(m, dist[k]);
        float sum = 0.0f;
        #pragma unroll
        for (int k = 0; k < 9; k++) {
            a[k] = (cell_sh[k] >= 0) ? fexp_neg(m - dist[k]) : 0.0f;
            sum += a[k];
        }
        float inv = 1.0f / sum;
        #pragma unroll
        for (int k = 0; k < 9; k++) {
            a[k] *= inv;
            aff_sh[k][t] = a[k];
        }
        __syncthreads();

        // ---- phase 2: warp-slice accumulation (lane = channel), f32x2 ----
        unsigned long long acc2[9];
        #pragma unroll
        for (int k = 0; k < 9; k++) acc2[k] = 0ull;
        {
            int p0 = wk * 32;
            const float* pr = &pix_sh[lane * PITCH + p0];
            #pragma unroll
            for (int i = 0; i < 32; i += 4) {
                ulonglong2 pv = *(const ulonglong2*)&pr[i];
                #pragma unroll
                for (int k = 0; k < 9; k++) {
                    ulonglong2 av = *(const ulonglong2*)&aff_sh[k][p0 + i];  // bcast
                    ffma2(acc2[k], av.x, pv.x);
                    ffma2(acc2[k], av.y, pv.y);
                }
            }
        }
        // denominators (read aff_sh before it is aliased); lane 0 holds result
        float dreg[2] = {0.0f, 0.0f};
        {
            int nd = 0;
            for (int k = wk; k < 9; k += 8) {
                float d = 0.0f;
                #pragma unroll
                for (int i2 = 0; i2 < 8; i2++) d += aff_sh[k][lane + (i2 << 5)];
                #pragma unroll
                for (int o = 16; o; o >>= 1) d += __shfl_xor_sync(0xffffffffu, d, o);
                dreg[nd++] = d;
            }
        }
        __syncthreads();                       // aff_sh + pix_sh reads done
        if (it == NITER - 1) {                 // stash affinities for the finale
            #pragma unroll
            for (int k = 0; k < 9; k++) pix_sh[k * 256 + t] = a[k];
        }
        float* s_acc = (float*)aff_sh;         // [8][9][32]
        #pragma unroll
        for (int k = 0; k < 9; k++)
            s_acc[(wk * 9 + k) * 32 + lane] = f2sum(acc2[k]);
        __syncthreads();

        // ---- tree reduce + single atomic per (neighbor, channel) + flags ----
        {
            int nd = 0;
            for (int k = wk; k < 9; k += 8) {
                int nc = cell_sh[k];
                float dv = dreg[nd++];
                if (nc >= 0) {
                    float v = 0.0f;
                    #pragma unroll
                    for (int w2 = 0; w2 < 8; w2++)
                        v += s_acc[(w2 * 9 + k) * 32 + lane];
                    atomicAdd(&g_num[it + 1][(bJ + nc) * C + lane], v);
                    if (lane == 0) atomicAdd(&g_den[it + 1][bJ + nc], dv);
                }
            }
        }
        __threadfence();                       // prior atomics visible
        for (int k = wk; k < 9; k += 8) {
            int nc = cell_sh[k];
            if (nc >= 0 && lane == 0) atomicAdd(&g_flag[it + 1][bJ + nc], 1u);
        }
    }

    // =======================================================================
    // Finale: gamma first (depends only on stashed aff), then fm + recon.
    // =======================================================================
    const float* aff2 = pix_sh;
    {
        int q = t & 63, jr = t >> 6;
        int r = q >> 2, colq = q & 3;
        size_t rowoff = (size_t)(jy * 16 + r) * W + jx * 16 + colq * 4;
        #pragma unroll 4
        for (int i = 0; i < 48; i++) {
            int jv  = jr + (i << 2);
            int jjy = jv >> 4, jjx = jv & 15;
            int ddy = jjy - jy, ddx = jjx - jx;
            float4 v = make_float4(0.f, 0.f, 0.f, 0.f);
            if (ddy >= -1 && ddy <= 1 && ddx >= -1 && ddx <= 1) {
                int k = (ddy + 1) * 3 + (ddx + 1);
                v = *(const float4*)&aff2[k * 256 + r * 16 + colq * 4];
            }
            __stcs((float4*)&gamma_out[((size_t)(bJ + jv)) * N + rowoff], v);
        }
    }

    // fm = num[10]/(den[10]+1e-6), gated on slot-10 flags
    for (int k = wk; k < 9; k += 8) {
        int nc = cell_sh[k];
        float fv = 0.0f;
        if (nc >= 0) {
            int idx = bJ + nc;
            poll_flag(&g_flag[NITER][idx], (unsigned)expect_sh[k]);
            fv = __ldcg(&g_num[NITER][idx * C + lane]) /
                 (__ldcg(&g_den[NITER][idx]) + 1e-6f);
        }
        s_sh[k][lane] = fv;
    }
    __syncthreads();

    // recon[b,c,n] = sum_k a[k] * fm[cell_k][c]   (f32x2)
    unsigned long long rec2[16];
    #pragma unroll
    for (int i = 0; i < 16; i++) rec2[i] = 0ull;
    #pragma unroll
    for (int k = 0; k < 9; k++) {
        unsigned long long ak2 = f2pack(a[k], a[k]);
        const ulonglong2* s2 = (const ulonglong2*)s_sh[k];
        #pragma unroll
        for (int c4 = 0; c4 < 8; c4++) {
            ulonglong2 sv = s2[c4];
            ffma2(rec2[2 * c4],     ak2, sv.x);
            ffma2(rec2[2 * c4 + 1], ak2, sv.y);
        }
    }
    #pragma unroll
    for (int i = 0; i < 16; i++) {
        float lo, hi;
        f2unpack(rec2[i], lo, hi);
        __stcs(&recon_out[((size_t)(b * C + 2 * i) * H + y) * W + x], lo);
        __stcs(&recon_out[((size_t)(b * C + 2 * i + 1) * H + y) * W + x], hi);
    }
}

// ---------------------------------------------------------------------------
extern "C" void kernel_launch(void* const* d_in, const int* in_sizes, int n_in,
                              void* d_out, int out_size) {
    (void)in_sizes; (void)n_in; (void)out_size;
    const float* feats = (const float*)d_in[0];
    float* gamma = (float*)d_out;
    float* recon = gamma + (size_t)B * J * N;

    k_reset<<<(SLOTS * B * J + 255) / 256, 256>>>();
    k_fused<<<NB, 256>>>(feats, gamma, recon);
}